// round 17
// baseline (speedup 1.0000x reference)
#include <cuda_runtime.h>
#include <cuda_fp16.h>
#include <cstdint>

#define N_NODES 100000
#define F_IN    500
#define HID     256
#define C_OUT   40
#define ALPHA0  0.1f
#define K_PAD   512
#define BK      32
#define NCHUNK  16
#define BM      128
#define N2      48
#define CAP     96          // per-row slot capacity (Poisson(23): overflow ~8.5 sigma)

// ---------------------------------------------------------------------------
// Device-global scratch (allocation-free rule)
// ---------------------------------------------------------------------------
__device__ float g_h2[(size_t)N_NODES * C_OUT];            // 16 MB
__device__ __align__(16) __half g_w1t[HID * K_PAD];        // W1^T fp16 (bias at k=500)
__device__ __align__(16) __half g_w2t[N2 * HID];           // W2^T fp16 (pad 40->48)
__device__ int  g_cnt[N_NODES + 1];
__device__ __align__(16) int2 g_slot[(size_t)N_NODES * CAP]; // 76.8 MB slotted CSR

// ---------------------------------------------------------------------------
// Helpers
// ---------------------------------------------------------------------------
__device__ __forceinline__ uint32_t smem_u32(const void* p) {
    uint32_t a;
    asm("{ .reg .u64 t; cvta.to.shared.u64 t, %1; cvt.u32.u64 %0, t; }" : "=r"(a) : "l"(p));
    return a;
}

__device__ __forceinline__ uint32_t pack_h2(float lo, float hi) {
    uint32_t r;
    asm("cvt.rn.f16x2.f32 %0, %1, %2;" : "=r"(r) : "f"(hi), "f"(lo));
    return r;
}

__device__ __forceinline__ void mma_f16(float d[4], const uint32_t a[4], const uint32_t b[2]) {
    asm volatile("mma.sync.aligned.m16n8k16.row.col.f32.f16.f16.f32 "
                 "{%0,%1,%2,%3},{%4,%5,%6,%7},{%8,%9},{%0,%1,%2,%3};"
                 : "+f"(d[0]), "+f"(d[1]), "+f"(d[2]), "+f"(d[3])
                 : "r"(a[0]), "r"(a[1]), "r"(a[2]), "r"(a[3]), "r"(b[0]), "r"(b[1]));
}

#define CP_ASYNC16(dst, src) \
    asm volatile("cp.async.cg.shared.global [%0], [%1], 16;" :: "r"(dst), "l"(src))
#define CP_COMMIT() asm volatile("cp.async.commit_group;" ::: "memory")
#define CP_WAIT0()  asm volatile("cp.async.wait_group 0;" ::: "memory")

// ---------------------------------------------------------------------------
// Dynamic SMEM layout (bytes)
// ---------------------------------------------------------------------------
#define APAD 40
#define SA(b) ((b) * 30720)
#define SB(b) ((b) * 30720 + 10240)
#define HPAD 264
#define SH    0
#define SW    67584
#define DSMEM_BYTES 92928

// ---------------------------------------------------------------------------
// Prep: fp16 images of W1^T (bias at k=500), W2^T (pad 40->48); zero g_cnt.
// ---------------------------------------------------------------------------
__global__ void prep_kernel(const float* __restrict__ W1,
                            const float* __restrict__ b1,
                            const float* __restrict__ W2)
{
    const int idx = blockIdx.x * blockDim.x + threadIdx.x;
    if (idx <= N_NODES) g_cnt[idx] = 0;
    if (idx < HID * K_PAD) {
        const int n = idx >> 9;
        const int k = idx & (K_PAD - 1);
        float v = 0.f;
        if (k < F_IN)       v = W1[(size_t)k * HID + n];
        else if (k == F_IN) v = b1[n];
        g_w1t[idx] = __float2half_rn(v);
    } else {
        const int i = idx - HID * K_PAD;
        if (i < N2 * HID) {
            const int n = i >> 8;
            const int k = i & 255;
            const float v = (n < C_OUT) ? W2[(size_t)k * C_OUT + n] : 0.f;
            g_w2t[i] = __float2half_rn(v);
        }
    }
}

// ---------------------------------------------------------------------------
// Slotted scatter: one atomic + one 8B store per edge.
// ---------------------------------------------------------------------------
__global__ void __launch_bounds__(256) scatter_kernel(
    const int* __restrict__ erow,
    const int* __restrict__ ecol,
    const float* __restrict__ eval,
    long long num_edges)
{
    const long long e = (long long)blockIdx.x * blockDim.x + threadIdx.x;
    if (e >= num_edges) return;
    const int r = erow[e];
    const int slot = atomicAdd(&g_cnt[r], 1);
    if (slot < CAP)
        g_slot[(size_t)r * CAP + slot] = make_int2(ecol[e], __float_as_int(eval[e]));
}

// ---------------------------------------------------------------------------
// Fused GEMM1(+bias+ReLU)+GEMM2(+bias), mma.sync fp16 (1-term both).
// Writes g_h2 only.
// ---------------------------------------------------------------------------
__global__ void __launch_bounds__(512, 1) fused_kernel(
    const float* __restrict__ x,
    const float* __restrict__ b2)
{
    extern __shared__ char dsm[];
    __shared__ float s_b2[C_OUT];
    const uint32_t smbase = smem_u32(dsm);
    const int tid  = threadIdx.x;
    const int lane = tid & 31, wid = tid >> 5;
    const int grp  = lane >> 2, tid4 = lane & 3;
    const int wm   = wid >> 2, wn = wid & 3;
    const int blockRow = blockIdx.x * BM;

    if (tid < C_OUT) s_b2[tid] = b2[tid];

    const int ar  = tid >> 2;
    const int akq = (tid & 3) * 8;
    const int brow = tid >> 1;
    const int bseg = tid & 1;

    float acc[2][8][4];
    #pragma unroll
    for (int i = 0; i < 2; i++)
        #pragma unroll
        for (int j = 0; j < 8; j++)
            #pragma unroll
            for (int q = 0; q < 4; q++)
                acc[i][j][q] = 0.f;

    const int grow = blockRow + ar;
    const bool rok = grow < N_NODES;
    const float* xrow = x + (size_t)grow * F_IN;

    float4 av[2];

    auto loadA = [&](int c) {
        const int gk0 = c * BK + akq;
        #pragma unroll
        for (int h = 0; h < 2; h++) {
            const int gk = gk0 + h * 4;
            float4 v = make_float4(0.f, 0.f, 0.f, 0.f);
            if (rok) {
                if (gk + 3 < F_IN) {
                    v = *(const float4*)(xrow + gk);
                } else {
                    v.x = (gk + 0 < F_IN) ? xrow[gk + 0] : (gk + 0 == F_IN ? 1.f : 0.f);
                    v.y = (gk + 1 < F_IN) ? xrow[gk + 1] : (gk + 1 == F_IN ? 1.f : 0.f);
                    v.z = (gk + 2 < F_IN) ? xrow[gk + 2] : (gk + 2 == F_IN ? 1.f : 0.f);
                    v.w = (gk + 3 < F_IN) ? xrow[gk + 3] : (gk + 3 == F_IN ? 1.f : 0.f);
                }
            }
            av[h] = v;
        }
    };
    auto stsA = [&](int buf) {
        #pragma unroll
        for (int h = 0; h < 2; h++) {
            const int o = ar * APAD + akq + h * 4;
            const uint32_t h0 = pack_h2(av[h].x, av[h].y);
            const uint32_t h1 = pack_h2(av[h].z, av[h].w);
            *(uint2*)(dsm + SA(buf) + o * 2) = make_uint2(h0, h1);
        }
    };
    auto cpB = [&](int c, int buf) {
        const uint32_t d0 = smbase + SB(buf) + brow * (APAD * 2) + bseg * 16;
        const __half* s0 = g_w1t + (size_t)brow * K_PAD + c * BK + bseg * 8;
        CP_ASYNC16(d0, s0);
        CP_ASYNC16(d0 + 32, s0 + 16);
    };
    auto mmaChunk = [&](int buf) {
        #pragma unroll
        for (int s = 0; s < 2; s++) {
            const int kk = s * 16 + tid4 * 2;
            uint32_t A[2][4];
            #pragma unroll
            for (int i = 0; i < 2; i++) {
                const int o1 = (wm * 32 + i * 16 + grp) * APAD + kk;
                const int o2 = o1 + 8 * APAD;
                A[i][0] = *(const uint32_t*)(dsm + SA(buf) + o1 * 2);
                A[i][1] = *(const uint32_t*)(dsm + SA(buf) + o2 * 2);
                A[i][2] = *(const uint32_t*)(dsm + SA(buf) + (o1 + 8) * 2);
                A[i][3] = *(const uint32_t*)(dsm + SA(buf) + (o2 + 8) * 2);
            }
            #pragma unroll
            for (int j = 0; j < 8; j++) {
                const int o = (wn * 64 + j * 8 + grp) * APAD + kk;
                uint32_t B[2];
                B[0] = *(const uint32_t*)(dsm + SB(buf) + o * 2);
                B[1] = *(const uint32_t*)(dsm + SB(buf) + (o + 8) * 2);
                #pragma unroll
                for (int i = 0; i < 2; i++)
                    mma_f16(acc[i][j], A[i], B);
            }
        }
    };

    // ---- prologue ----
    loadA(0);
    cpB(0, 0);
    CP_COMMIT();
    stsA(0);
    CP_WAIT0();
    __syncthreads();

    // ---- GEMM1 mainloop ----
    for (int c = 0; c < NCHUNK; c++) {
        const int cur = c & 1, nxt = cur ^ 1;
        if (c + 1 < NCHUNK) {
            loadA(c + 1);
            cpB(c + 1, nxt);
            CP_COMMIT();
        }
        mmaChunk(cur);
        if (c + 1 < NCHUNK) {
            stsA(nxt);
            CP_WAIT0();
        }
        __syncthreads();
    }

    // ---- epilogue 1: ReLU + fp16 -> sH ----
    #pragma unroll
    for (int i = 0; i < 2; i++) {
        const int r1 = wm * 32 + i * 16 + grp;
        #pragma unroll
        for (int j = 0; j < 8; j++) {
            const int col = wn * 64 + j * 8 + tid4 * 2;
            const float f0 = fmaxf(acc[i][j][0], 0.f), f1 = fmaxf(acc[i][j][1], 0.f);
            const float f2 = fmaxf(acc[i][j][2], 0.f), f3 = fmaxf(acc[i][j][3], 0.f);
            const int o1 = r1 * HPAD + col;
            const int o2 = o1 + 8 * HPAD;
            *(uint32_t*)(dsm + SH + o1 * 2) = pack_h2(f0, f1);
            *(uint32_t*)(dsm + SH + o2 * 2) = pack_h2(f2, f3);
        }
    }
    // ---- W2 image -> sW ----
    {
        const int n  = tid >> 3;
        const int kq = (tid & 7) * 32;
        if (n < N2) {
            #pragma unroll
            for (int q = 0; q < 4; q++) {
                const uint4 v = *(const uint4*)(g_w2t + n * HID + kq + q * 8);
                *(uint4*)(dsm + SW + (n * HPAD + kq + q * 8) * 2) = v;
            }
        }
    }
    __syncthreads();

    // ---- GEMM2 (1-term): all 16 warps ----
    {
        const int rg = wid & 7;
        const int nh = wid >> 3;
        float acc2[3][4];
        #pragma unroll
        for (int j = 0; j < 3; j++)
            #pragma unroll
            for (int q = 0; q < 4; q++)
                acc2[j][q] = 0.f;

        #pragma unroll
        for (int s = 0; s < 16; s++) {
            const int kk = s * 16 + tid4 * 2;
            const int o1 = (rg * 16 + grp) * HPAD + kk;
            const int o2 = o1 + 8 * HPAD;
            uint32_t A[4];
            A[0] = *(const uint32_t*)(dsm + SH + o1 * 2);
            A[1] = *(const uint32_t*)(dsm + SH + o2 * 2);
            A[2] = *(const uint32_t*)(dsm + SH + (o1 + 8) * 2);
            A[3] = *(const uint32_t*)(dsm + SH + (o2 + 8) * 2);
            #pragma unroll
            for (int j = 0; j < 3; j++) {
                const int ob = ((nh * 3 + j) * 8 + grp) * HPAD + kk;
                uint32_t B[2];
                B[0] = *(const uint32_t*)(dsm + SW + ob * 2);
                B[1] = *(const uint32_t*)(dsm + SW + (ob + 8) * 2);
                mma_f16(acc2[j], A, B);
            }
        }

        // ---- epilogue 2: g_h2 = D2 + b2 ----
        const int r1 = blockRow + rg * 16 + grp;
        const int r2 = r1 + 8;
        #pragma unroll
        for (int j = 0; j < 3; j++) {
            const int col = (nh * 3 + j) * 8 + tid4 * 2;
            if (col >= C_OUT) continue;
            const float b0 = s_b2[col], b1v = s_b2[col + 1];
            if (r1 < N_NODES)
                *(float2*)(g_h2 + (size_t)r1 * C_OUT + col) =
                    make_float2(acc2[j][0] + b0, acc2[j][1] + b1v);
            if (r2 < N_NODES)
                *(float2*)(g_h2 + (size_t)r2 * C_OUT + col) =
                    make_float2(acc2[j][2] + b0, acc2[j][3] + b1v);
        }
    }
}

// ---------------------------------------------------------------------------
// Fused gather-SpMM + log_softmax, split-edge variant.
// 640 threads = 32 nodes/block: 10 slices x 2 edge-halves per node.
// Each thread walks ~deg/2 edges; halves merge in smem; half-0 threads run
// the 10-lane log_softmax reduction. Only block-level __syncthreads used
// (no divergent warp syncs -- that hung R16).
// ---------------------------------------------------------------------------
__global__ void __launch_bounds__(640) gather_lsm_kernel(float* __restrict__ out)
{
    __shared__ float4 s_acc[32][10];
    __shared__ float  s_max[32][10];
    __shared__ float  s_sum[32][10];

    const int tid = threadIdx.x;
    const int nl  = tid / 20;            // node_local 0..31
    const int r20 = tid % 20;
    const int sub = r20 % 10;            // slice 0..9
    const int eh  = r20 / 10;            // edge half 0..1
    const int node = blockIdx.x * 32 + nl;
    const bool ok = node < N_NODES;

    float4 acc = make_float4(0.f, 0.f, 0.f, 0.f);

    if (ok) {
        const int deg = min(g_cnt[node], CAP);
        const int half = (deg + 1) >> 1;
        const int lo = eh ? half : 0;
        const int hi = eh ? deg : half;
        const int2* base = g_slot + (size_t)node * CAP;

        int i = lo;
        for (; i + 1 < hi; i += 2) {
            const int2 p0 = __ldg(&base[i]);
            const int2 p1 = __ldg(&base[i + 1]);
            const float4 h0 = __ldg(&reinterpret_cast<const float4*>(g_h2 + (size_t)p0.x * C_OUT)[sub]);
            const float4 h1 = __ldg(&reinterpret_cast<const float4*>(g_h2 + (size_t)p1.x * C_OUT)[sub]);
            const float v0 = __int_as_float(p0.y);
            const float v1 = __int_as_float(p1.y);
            acc.x += v0 * h0.x + v1 * h1.x;
            acc.y += v0 * h0.y + v1 * h1.y;
            acc.z += v0 * h0.z + v1 * h1.z;
            acc.w += v0 * h0.w + v1 * h1.w;
        }
        if (i < hi) {
            const int2 p = __ldg(&base[i]);
            const float4 h = __ldg(&reinterpret_cast<const float4*>(g_h2 + (size_t)p.x * C_OUT)[sub]);
            const float v = __int_as_float(p.y);
            acc.x += v * h.x;
            acc.y += v * h.y;
            acc.z += v * h.z;
            acc.w += v * h.w;
        }

        if (eh == 0) {
            const float4 hs = __ldg(&reinterpret_cast<const float4*>(g_h2 + (size_t)node * C_OUT)[sub]);
            acc.x += ALPHA0 * hs.x;
            acc.y += ALPHA0 * hs.y;
            acc.z += ALPHA0 * hs.z;
            acc.w += ALPHA0 * hs.w;
        }
    }

    // merge the two halves (block-level syncs only)
    if (eh == 1) s_acc[nl][sub] = acc;
    __syncthreads();
    if (eh == 0) {
        const float4 o = s_acc[nl][sub];
        acc.x += o.x; acc.y += o.y; acc.z += o.z; acc.w += o.w;
        s_max[nl][sub] = fmaxf(fmaxf(acc.x, acc.y), fmaxf(acc.z, acc.w));
    }
    __syncthreads();

    float m = s_max[nl][0];
    #pragma unroll
    for (int t = 1; t < 10; t++) m = fmaxf(m, s_max[nl][t]);

    if (eh == 0)
        s_sum[nl][sub] = expf(acc.x - m) + expf(acc.y - m) + expf(acc.z - m) + expf(acc.w - m);
    __syncthreads();

    if (eh == 0 && ok) {
        float s = s_sum[nl][0];
        #pragma unroll
        for (int t = 1; t < 10; t++) s += s_sum[nl][t];
        const float lse = m + logf(s);
        reinterpret_cast<float4*>(out + (size_t)node * C_OUT)[sub] =
            make_float4(acc.x - lse, acc.y - lse, acc.z - lse, acc.w - lse);
    }
}

// ---------------------------------------------------------------------------
// Inputs: x, W1, b1, W2, b2, edge_row, edge_col, edge_val
// Scatter runs on a side stream concurrently with the fused GEMM.
// ---------------------------------------------------------------------------
extern "C" void kernel_launch(void* const* d_in, const int* in_sizes, int n_in,
                              void* d_out, int out_size)
{
    const float* x    = (const float*)d_in[0];
    const float* W1   = (const float*)d_in[1];
    const float* b1   = (const float*)d_in[2];
    const float* W2   = (const float*)d_in[3];
    const float* b2   = (const float*)d_in[4];
    const int*   erow = (const int*)d_in[5];
    const int*   ecol = (const int*)d_in[6];
    const float* eval = (const float*)d_in[7];
    float* out = (float*)d_out;

    const long long E = in_sizes[5];

    static cudaStream_t s2 = nullptr;
    static cudaEvent_t evFork = nullptr, evJoin = nullptr;
    if (!s2) {   // first call = correctness run (not captured); objects persist
        cudaStreamCreateWithFlags(&s2, cudaStreamNonBlocking);
        cudaEventCreateWithFlags(&evFork, cudaEventDisableTiming);
        cudaEventCreateWithFlags(&evJoin, cudaEventDisableTiming);
        cudaFuncSetAttribute(fused_kernel,
                             cudaFuncAttributeMaxDynamicSharedMemorySize, DSMEM_BYTES);
    }

    // prep (zeroes g_cnt, builds weight images) on main stream
    {
        const int total = HID * K_PAD + N2 * HID;   // >= N_NODES+1
        prep_kernel<<<(total + 255) / 256, 256>>>(W1, b1, W2);
    }

    // fork: scatter on s2 (depends on prep's g_cnt zeroing)
    cudaEventRecord(evFork, 0);
    cudaStreamWaitEvent(s2, evFork, 0);
    scatter_kernel<<<(int)((E + 255) / 256), 256, 0, s2>>>(erow, ecol, eval, E);
    cudaEventRecord(evJoin, s2);

    // fused GEMM1+GEMM2 -> g_h2 on main stream (concurrent with scatter)
    {
        const int blocks = (N_NODES + BM - 1) / BM;
        fused_kernel<<<blocks, 512, DSMEM_BYTES>>>(x, b2);
    }

    // join: gather needs both g_slot (s2) and g_h2 (main)
    cudaStreamWaitEvent(0, evJoin, 0);

    // fused gather-SpMM + log_softmax (split-edge): out = log_softmax(alpha*h2 + agg)
    {
        const int blocks = (N_NODES + 31) / 32;
        gather_lsm_kernel<<<blocks, 640>>>(out);
    }
}